// round 5
// baseline (speedup 1.0000x reference)
#include <cuda_runtime.h>

#define NN 100000
#define EE 1600000
#define CAP 64

// ---- scratch (static __device__ allocations only, per harness rules) ----
__device__ int   g_deg[NN];
__device__ int   g_adj[NN * CAP];     // per-dst src lists (counting bucket sort)
__device__ float g_U[NN * 64];        // per-node precomputed  x@(Wa_top-Wa_bot)+ba
__device__ float g_V[NN * 64];        // per-node precomputed  x@Wa_bot
__device__ float g_H[NN * 64];        // layer-1 output (post relu/fill)

// ---------------------------------------------------------------- zero degs
__global__ void k_zero() {
    int i = blockIdx.x * blockDim.x + threadIdx.x;
    if (i < NN) g_deg[i] = 0;
}

// ------------------------------------------------- bucket edges by dst node
__global__ void k_scatter(const int* __restrict__ ei) {
    int e = blockIdx.x * blockDim.x + threadIdx.x;
    if (e >= EE) return;
    int s = ei[e];          // src row
    int d = ei[EE + e];     // dst row
    int p = atomicAdd(&g_deg[d], 1);
    if (p < CAP) g_adj[d * CAP + p] = s;
}

// ------------------------------------- layer-1 per-node U,V from x (K = 7)
__global__ void __launch_bounds__(128) k_uv1(const float* __restrict__ x,
                                             const float* __restrict__ W1a,
                                             const float* __restrict__ b1a) {
    __shared__ float sW[14 * 64];
    __shared__ float sb[64];
    for (int t = threadIdx.x; t < 14 * 64; t += blockDim.x) sW[t] = W1a[t];
    for (int t = threadIdx.x; t < 64; t += blockDim.x) sb[t] = b1a[t];
    __syncthreads();

    int warp = threadIdx.x >> 5, lane = threadIdx.x & 31;
    int i = blockIdx.x * 4 + warp;
    if (i >= NN) return;
    int c0 = 2 * lane, c1 = c0 + 1;

    float xv[7];
#pragma unroll
    for (int k = 0; k < 7; k++) xv[k] = x[i * 7 + k];   // broadcast in warp

    float u0 = sb[c0], u1 = sb[c1], v0 = 0.f, v1 = 0.f;
#pragma unroll
    for (int k = 0; k < 7; k++) {
        float wt0 = sW[k * 64 + c0], wt1 = sW[k * 64 + c1];
        float wb0 = sW[(7 + k) * 64 + c0], wb1 = sW[(7 + k) * 64 + c1];
        u0 = fmaf(xv[k], wt0 - wb0, u0);
        u1 = fmaf(xv[k], wt1 - wb1, u1);
        v0 = fmaf(xv[k], wb0, v0);
        v1 = fmaf(xv[k], wb1, v1);
    }
    *(float2*)&g_U[i * 64 + c0] = make_float2(u0, u1);
    *(float2*)&g_V[i * 64 + c0] = make_float2(v0, v1);
}

// ------------------------------------ layer-2 per-node U,V from H (K = 64)
__global__ void __launch_bounds__(128) k_uv2(const float* __restrict__ W2a,
                                             const float* __restrict__ b2a) {
    __shared__ float sWt[64 * 64];
    __shared__ float sWb[64 * 64];
    __shared__ float sb[64];
    __shared__ float sh[4][64];
    for (int t = threadIdx.x; t < 4096; t += blockDim.x) {
        sWt[t] = W2a[t];
        sWb[t] = W2a[4096 + t];
    }
    for (int t = threadIdx.x; t < 64; t += blockDim.x) sb[t] = b2a[t];
    __syncthreads();

    int warp = threadIdx.x >> 5, lane = threadIdx.x & 31;
    int c0 = 2 * lane, c1 = c0 + 1;
    float* shw = sh[warp];
    int nwarps = gridDim.x * 4;

    for (int i = blockIdx.x * 4 + warp; i < NN; i += nwarps) {
        float2 h2 = *(const float2*)&g_H[i * 64 + c0];
        shw[c0] = h2.x; shw[c1] = h2.y;
        __syncwarp();
        float u0 = sb[c0], u1 = sb[c1], v0 = 0.f, v1 = 0.f;
        const float4* h4p = (const float4*)shw;
#pragma unroll
        for (int kk = 0; kk < 16; kk++) {
            float4 h4 = h4p[kk];
#pragma unroll
            for (int q = 0; q < 4; q++) {
                int k = 4 * kk + q;
                float hk = (q == 0) ? h4.x : (q == 1) ? h4.y : (q == 2) ? h4.z : h4.w;
                float2 wt = *(const float2*)&sWt[k * 64 + c0];
                float2 wb = *(const float2*)&sWb[k * 64 + c0];
                u0 = fmaf(hk, wt.x - wb.x, u0);
                u1 = fmaf(hk, wt.y - wb.y, u1);
                v0 = fmaf(hk, wb.x, v0);
                v1 = fmaf(hk, wb.y, v1);
            }
        }
        __syncwarp();
        *(float2*)&g_U[i * 64 + c0] = make_float2(u0, u1);
        *(float2*)&g_V[i * 64 + c0] = make_float2(v0, v1);
    }
}

// -------- hot kernel: per-node max-aggregate of relu(U[i]+V[j]) @ Wb + bb
// warp per node, 2 output channels per thread, Wb columns in registers,
// t broadcast through smem. acc starts at 0 => fused relu + empty-node fill.
template <bool FINAL>
__global__ void __launch_bounds__(128) k_layer(const float* __restrict__ Wb,
                                               const float* __restrict__ bb,
                                               const float* __restrict__ Wl,
                                               const float* __restrict__ bl,
                                               float* __restrict__ out) {
    __shared__ float sW[64 * 64];
    __shared__ float st[4][64];
    for (int t = threadIdx.x; t < 4096; t += blockDim.x) sW[t] = Wb[t];
    __syncthreads();

    int warp = threadIdx.x >> 5, lane = threadIdx.x & 31;
    int c0 = 2 * lane, c1 = c0 + 1;

    float w0[64], w1[64];
#pragma unroll
    for (int k = 0; k < 64; k++) {
        w0[k] = sW[k * 64 + c0];
        w1[k] = sW[k * 64 + c1];
    }
    float bb0 = bb[c0], bb1 = bb[c1];
    float wl0 = 0.f, wl1 = 0.f, blv = 0.f;
    if (FINAL) { wl0 = Wl[c0]; wl1 = Wl[c1]; blv = bl[0]; }

    float* stw = st[warp];
    int nwarps = gridDim.x * 4;

    for (int i = blockIdx.x * 4 + warp; i < NN; i += nwarps) {
        int dg = g_deg[i];
        if (dg > CAP) dg = CAP;
        const int* adj = &g_adj[i * CAP];
        float2 uu = *(const float2*)&g_U[i * 64 + c0];
        float a0 = 0.f, a1 = 0.f;

        float2 vp = make_float2(0.f, 0.f);
        if (dg > 0) {
            int j0 = adj[0];
            vp = *(const float2*)&g_V[j0 * 64 + c0];
        }
        for (int e = 0; e < dg; e++) {
            float2 vv = vp;
            if (e + 1 < dg) {
                int jn = adj[e + 1];
                vp = *(const float2*)&g_V[jn * 64 + c0];   // prefetch next edge
            }
            float t0 = fmaxf(uu.x + vv.x, 0.f);
            float t1 = fmaxf(uu.y + vv.y, 0.f);
            stw[c0] = t0; stw[c1] = t1;
            __syncwarp();
            float z0 = 0.f, z1 = 0.f, z2 = 0.f, z3 = 0.f;
            float y0 = 0.f, y1 = 0.f, y2 = 0.f, y3 = 0.f;
            const float4* t4p = (const float4*)stw;
#pragma unroll
            for (int kk = 0; kk < 16; kk++) {
                float4 t4 = t4p[kk];
                z0 = fmaf(w0[4 * kk + 0], t4.x, z0);
                z1 = fmaf(w0[4 * kk + 1], t4.y, z1);
                z2 = fmaf(w0[4 * kk + 2], t4.z, z2);
                z3 = fmaf(w0[4 * kk + 3], t4.w, z3);
                y0 = fmaf(w1[4 * kk + 0], t4.x, y0);
                y1 = fmaf(w1[4 * kk + 1], t4.y, y1);
                y2 = fmaf(w1[4 * kk + 2], t4.z, y2);
                y3 = fmaf(w1[4 * kk + 3], t4.w, y3);
            }
            __syncwarp();
            a0 = fmaxf(a0, (z0 + z1) + (z2 + z3) + bb0);
            a1 = fmaxf(a1, (y0 + y1) + (y2 + y3) + bb1);
        }

        if (FINAL) {
            float p = a0 * wl0 + a1 * wl1;
#pragma unroll
            for (int off = 16; off; off >>= 1)
                p += __shfl_xor_sync(0xffffffffu, p, off);
            if (lane == 0) out[i] = p + blv;
        } else {
            *(float2*)&g_H[i * 64 + c0] = make_float2(a0, a1);
        }
    }
}

extern "C" void kernel_launch(void* const* d_in, const int* in_sizes, int n_in,
                              void* d_out, int out_size) {
    const float* x   = (const float*)d_in[0];
    const int*   ei  = (const int*)d_in[1];
    const float* W1a = (const float*)d_in[2];
    const float* b1a = (const float*)d_in[3];
    const float* W1b = (const float*)d_in[4];
    const float* b1b = (const float*)d_in[5];
    const float* W2a = (const float*)d_in[6];
    const float* b2a = (const float*)d_in[7];
    const float* W2b = (const float*)d_in[8];
    const float* b2b = (const float*)d_in[9];
    const float* Wl  = (const float*)d_in[10];
    const float* bl  = (const float*)d_in[11];
    float* out = (float*)d_out;

    k_zero<<<(NN + 255) / 256, 256>>>();
    k_scatter<<<(EE + 255) / 256, 256>>>(ei);
    k_uv1<<<(NN + 3) / 4, 128>>>(x, W1a, b1a);
    k_layer<false><<<1184, 128>>>(W1b, b1b, nullptr, nullptr, nullptr);
    k_uv2<<<888, 128>>>(W2a, b2a);
    k_layer<true><<<1184, 128>>>(W2b, b2b, Wl, bl, out);
}

// round 7
// speedup vs baseline: 1.3700x; 1.3700x over previous
#include <cuda_runtime.h>
#include <cstdint>
#include <math_constants.h>

#define NN 100000
#define EE 1600000
#define TILE 128
#define NTILE (EE / TILE)          // 12500 exactly
#define NSCANB 98
#define BSTRIDE 68                 // floats per B row  [edge][kperm]
#define DSTRIDE 133                // floats per D row  [ch][edge]
#define SMEM_WORDS (TILE * BSTRIDE + 64 * DSTRIDE + TILE)
#define SMEM_BYTES (SMEM_WORDS * 4)

// ---------------- static device scratch ----------------------------------
__device__ int      g_cnt[NN];
__device__ int      g_off[NN];
__device__ int      g_bsum[NSCANB];
__device__ int      g_srcs[EE];
__device__ int      g_enode[EE];
__device__ float    g_U[NN * 64];
__device__ float    g_V[NN * 64];
__device__ float    g_H[NN * 64];
__device__ unsigned g_agg[NN * 64];

// ---------------- helpers -------------------------------------------------
__device__ __forceinline__ uint32_t tf32(float f) {
    uint32_t r;
    asm("cvt.rna.tf32.f32 %0, %1;" : "=r"(r) : "f"(f));
    return r;
}
__device__ __forceinline__ unsigned ord_enc(float f) {
    unsigned u = __float_as_uint(f);
    return (u & 0x80000000u) ? ~u : (u | 0x80000000u);
}
__device__ __forceinline__ float ord_dec(unsigned u) {
    return (u & 0x80000000u) ? __uint_as_float(u ^ 0x80000000u) : __uint_as_float(~u);
}
__device__ __forceinline__ void redmax(unsigned* p, unsigned v) {
    asm volatile("red.global.max.u32 [%0], %1;" :: "l"(p), "r"(v) : "memory");
}
// k-permutation: (k, k+4) adjacent ->  col = (k&3)*2 + ((k>>2)&1) + (k>>3)*8
__device__ __forceinline__ int kperm(int k) {
    return ((k & 3) << 1) + ((k >> 2) & 1) + ((k >> 3) << 3);
}

// ---------------- preprocessing ------------------------------------------
__global__ void k_zero() {
    int i = blockIdx.x * blockDim.x + threadIdx.x;
    if (i < NN) g_cnt[i] = 0;
}
__global__ void k_count(const int* __restrict__ ei) {
    int e = blockIdx.x * blockDim.x + threadIdx.x;
    if (e < EE) atomicAdd(&g_cnt[ei[EE + e]], 1);
}
__global__ void __launch_bounds__(1024) k_scan1() {
    __shared__ int ws[32];
    int i = blockIdx.x * 1024 + threadIdx.x;
    int v = (i < NN) ? g_cnt[i] : 0;
    int x = v;
#pragma unroll
    for (int o = 1; o < 32; o <<= 1) {
        int y = __shfl_up_sync(0xffffffffu, x, o);
        if ((threadIdx.x & 31) >= o) x += y;
    }
    if ((threadIdx.x & 31) == 31) ws[threadIdx.x >> 5] = x;
    __syncthreads();
    if (threadIdx.x < 32) {
        int y = ws[threadIdx.x];
#pragma unroll
        for (int o = 1; o < 32; o <<= 1) {
            int z = __shfl_up_sync(0xffffffffu, y, o);
            if (threadIdx.x >= o) y += z;
        }
        ws[threadIdx.x] = y;
    }
    __syncthreads();
    int wsum = (threadIdx.x >= 32) ? ws[(threadIdx.x >> 5) - 1] : 0;
    int incl = x + wsum;
    if (i < NN) g_off[i] = incl - v;
    if (threadIdx.x == 1023) g_bsum[blockIdx.x] = incl;
}
__global__ void k_scan2() {
    if (threadIdx.x == 0) {
        int run = 0;
        for (int b = 0; b < NSCANB; b++) { int t = g_bsum[b]; g_bsum[b] = run; run += t; }
    }
}
__global__ void __launch_bounds__(1024) k_scan3() {
    int i = blockIdx.x * 1024 + threadIdx.x;
    if (i < NN) g_off[i] += g_bsum[blockIdx.x];
}
__global__ void k_fill(const int* __restrict__ ei) {
    int e = blockIdx.x * blockDim.x + threadIdx.x;
    if (e >= EE) return;
    int s = ei[e], d = ei[EE + e];
    int p = atomicAdd(&g_cnt[d], 1);
    int idx = g_off[d] + p;
    g_srcs[idx] = s;
    g_enode[idx] = d;
}
__global__ void __launch_bounds__(1024) k_zeroagg() {
    int i = blockIdx.x * 1024 + threadIdx.x;
    if (i < NN * 64) g_agg[i] = 0u;
}

// ---------------- per-node U,V layer 1 (K=7) ------------------------------
__global__ void __launch_bounds__(128) k_uv1(const float* __restrict__ x,
                                             const float* __restrict__ W1a,
                                             const float* __restrict__ b1a) {
    __shared__ float sW[14 * 64];
    __shared__ float sb[64];
    for (int t = threadIdx.x; t < 14 * 64; t += 128) sW[t] = W1a[t];
    for (int t = threadIdx.x; t < 64; t += 128) sb[t] = b1a[t];
    __syncthreads();
    int warp = threadIdx.x >> 5, lane = threadIdx.x & 31;
    int i = blockIdx.x * 4 + warp;
    if (i >= NN) return;
    int c0 = 2 * lane, c1 = c0 + 1;
    float xv[7];
#pragma unroll
    for (int k = 0; k < 7; k++) xv[k] = x[i * 7 + k];
    float u0 = sb[c0], u1 = sb[c1], v0 = 0.f, v1 = 0.f;
#pragma unroll
    for (int k = 0; k < 7; k++) {
        float wt0 = sW[k * 64 + c0], wt1 = sW[k * 64 + c1];
        float wb0 = sW[(7 + k) * 64 + c0], wb1 = sW[(7 + k) * 64 + c1];
        u0 = fmaf(xv[k], wt0 - wb0, u0);
        u1 = fmaf(xv[k], wt1 - wb1, u1);
        v0 = fmaf(xv[k], wb0, v0);
        v1 = fmaf(xv[k], wb1, v1);
    }
    *(float2*)&g_U[i * 64 + c0] = make_float2(u0, u1);
    *(float2*)&g_V[i * 64 + c0] = make_float2(v0, v1);
}

// ---------------- per-node U,V layer 2 (K=64, from g_H) -------------------
__global__ void __launch_bounds__(128) k_uv2(const float* __restrict__ W2a,
                                             const float* __restrict__ b2a) {
    __shared__ float sWt[64 * 64];
    __shared__ float sWb[64 * 64];
    __shared__ float sb[64];
    __shared__ float sh[4][64];
    for (int t = threadIdx.x; t < 4096; t += 128) {
        sWt[t] = W2a[t];
        sWb[t] = W2a[4096 + t];
    }
    for (int t = threadIdx.x; t < 64; t += 128) sb[t] = b2a[t];
    __syncthreads();
    int warp = threadIdx.x >> 5, lane = threadIdx.x & 31;
    int c0 = 2 * lane, c1 = c0 + 1;
    float* shw = sh[warp];
    int nwarps = gridDim.x * 4;
    for (int i = blockIdx.x * 4 + warp; i < NN; i += nwarps) {
        float2 h2 = *(const float2*)&g_H[i * 64 + c0];
        shw[c0] = h2.x; shw[c1] = h2.y;
        __syncwarp();
        float u0 = sb[c0], u1 = sb[c1], v0 = 0.f, v1 = 0.f;
        const float4* h4p = (const float4*)shw;
#pragma unroll
        for (int kk = 0; kk < 16; kk++) {
            float4 h4 = h4p[kk];
#pragma unroll
            for (int q = 0; q < 4; q++) {
                int k = 4 * kk + q;
                float hk = (q == 0) ? h4.x : (q == 1) ? h4.y : (q == 2) ? h4.z : h4.w;
                float2 wt = *(const float2*)&sWt[k * 64 + c0];
                float2 wb = *(const float2*)&sWb[k * 64 + c0];
                u0 = fmaf(hk, wt.x - wb.x, u0);
                u1 = fmaf(hk, wt.y - wb.y, u1);
                v0 = fmaf(hk, wb.x, v0);
                v1 = fmaf(hk, wb.y, v1);
            }
        }
        __syncwarp();
        *(float2*)&g_U[i * 64 + c0] = make_float2(u0, u1);
        *(float2*)&g_V[i * 64 + c0] = make_float2(v0, v1);
    }
}

// ---------------- hot kernel: tf32 mma.sync over sorted edge tiles --------
// Per tile: D[64 ch][128 edges] = Wb^T(64x64) @ B(64x128),
//   B[k][e] = relu(U[dst(e)][k] + V[src(e)][k])  (tf32)
// m16n8k8 fragments; A preloaded in regs; B smem [e][kperm]; D smem [ch][e].
__global__ void __launch_bounds__(256) k_mma(const float* __restrict__ Wb) {
    extern __shared__ uint32_t smem[];
    uint32_t* Bs = smem;                         // [128][BSTRIDE]
    float*    Ds = (float*)(smem + TILE * BSTRIDE);   // [64][DSTRIDE]
    int*   snode = (int*)(smem + TILE * BSTRIDE + 64 * DSTRIDE); // [128]

    const int tid = threadIdx.x, wid = tid >> 5, lane = tid & 31;
    const int g = lane >> 2, r = lane & 3;       // groupID, threadID_in_group
    const int m0 = 16 * (wid & 3);               // channel tile base
    const int n0b = 64 * (wid >> 2);             // edge half base

    // ---- preload A fragments (Wb^T, rna-tf32): aw[kk][0..3]
    uint32_t aw[8][4];
#pragma unroll
    for (int kk = 0; kk < 8; kk++) {
        int k0 = kk * 8 + r;
        aw[kk][0] = tf32(Wb[k0 * 64 + m0 + g]);
        aw[kk][1] = tf32(Wb[k0 * 64 + m0 + g + 8]);
        aw[kk][2] = tf32(Wb[(k0 + 4) * 64 + m0 + g]);
        aw[kk][3] = tf32(Wb[(k0 + 4) * 64 + m0 + g + 8]);
    }
    // build-phase per-lane constants
    const int colA = kperm(2 * lane), colB = kperm(2 * lane + 1);

    for (int tt = blockIdx.x; tt < NTILE; tt += gridDim.x) {
        // ---- build B tile: warp wid -> edges [wid*16, wid*16+16)
        {
            int e0w = tt * TILE + wid * 16;
            int myv = (lane < 16) ? g_srcs[e0w + lane] : g_enode[e0w + (lane - 16)];
            if (lane >= 16) snode[wid * 16 + lane - 16] = myv;
#pragma unroll 4
            for (int j = 0; j < 16; j++) {
                int s = __shfl_sync(0xffffffffu, myv, j);
                int d = __shfl_sync(0xffffffffu, myv, 16 + j);
                float2 u = *(const float2*)&g_U[d * 64 + 2 * lane];
                float2 v = *(const float2*)&g_V[s * 64 + 2 * lane];
                int e = wid * 16 + j;
                Bs[e * BSTRIDE + colA] = tf32(fmaxf(u.x + v.x, 0.f));
                Bs[e * BSTRIDE + colB] = tf32(fmaxf(u.y + v.y, 0.f));
            }
        }
        __syncthreads();

        // ---- MMA: warp covers ch [m0,m0+16) x edges [n0b, n0b+64)
#pragma unroll
        for (int j = 0; j < 8; j++) {
            int n0 = n0b + 8 * j;
            float c0 = 0.f, c1 = 0.f, c2 = 0.f, c3 = 0.f;
            const uint32_t* bp = &Bs[(n0 + g) * BSTRIDE + 2 * r];
#pragma unroll
            for (int kk = 0; kk < 8; kk++) {
                uint32_t b0, b1;
                asm("ld.shared.v2.b32 {%0,%1}, [%2];"
                    : "=r"(b0), "=r"(b1) : "r"((uint32_t)__cvta_generic_to_shared(bp + 8 * kk)));
                asm volatile(
                    "mma.sync.aligned.m16n8k8.row.col.f32.tf32.tf32.f32 "
                    "{%0,%1,%2,%3}, {%4,%5,%6,%7}, {%8,%9}, {%0,%1,%2,%3};"
                    : "+f"(c0), "+f"(c1), "+f"(c2), "+f"(c3)
                    : "r"(aw[kk][0]), "r"(aw[kk][1]), "r"(aw[kk][2]), "r"(aw[kk][3]),
                      "r"(b0), "r"(b1));
            }
            int e = n0 + 2 * r;
            Ds[(m0 + g) * DSTRIDE + e]     = c0;
            Ds[(m0 + g) * DSTRIDE + e + 1] = c1;
            Ds[(m0 + g + 8) * DSTRIDE + e]     = c2;
            Ds[(m0 + g + 8) * DSTRIDE + e + 1] = c3;
        }
        __syncthreads();

        // ---- epilogue: segmented max; thread = (channel, edge-quarter)
        {
            int ch = tid & 63, qq = tid >> 6;
            int e0 = qq * 32;
            float acc = -CUDART_INF_F;
            int cur = snode[e0];
            const float* dp = &Ds[ch * DSTRIDE];
#pragma unroll 8
            for (int e = e0; e < e0 + 32; e++) {
                int nid = snode[e];
                float v = dp[e];
                if (nid != cur) {
                    redmax(&g_agg[cur * 64 + ch], ord_enc(acc));
                    cur = nid;
                    acc = -CUDART_INF_F;
                }
                acc = fmaxf(acc, v);
            }
            redmax(&g_agg[cur * 64 + ch], ord_enc(acc));
        }
        __syncthreads();
    }
}

// ---------------- post passes ---------------------------------------------
__global__ void __launch_bounds__(1024) k_post1(const float* __restrict__ b1b) {
    int i = blockIdx.x * 1024 + threadIdx.x;
    if (i >= NN * 64) return;
    float v = ord_dec(g_agg[i]) + __ldg(&b1b[i & 63]);
    g_H[i] = fmaxf(v, 0.f);                      // NaN (empty node) -> 0
}
__global__ void __launch_bounds__(128) k_final(const float* __restrict__ b2b,
                                               const float* __restrict__ Wl,
                                               const float* __restrict__ bl,
                                               float* __restrict__ out) {
    int warp = threadIdx.x >> 5, lane = threadIdx.x & 31;
    int i = blockIdx.x * 4 + warp;
    if (i >= NN) return;
    int c0 = 2 * lane, c1 = c0 + 1;
    float a0 = fmaxf(ord_dec(g_agg[i * 64 + c0]) + b2b[c0], 0.f);
    float a1 = fmaxf(ord_dec(g_agg[i * 64 + c1]) + b2b[c1], 0.f);
    float p = a0 * Wl[c0] + a1 * Wl[c1];
#pragma unroll
    for (int off = 16; off; off >>= 1) p += __shfl_xor_sync(0xffffffffu, p, off);
    if (lane == 0) out[i] = p + bl[0];
}

extern "C" void kernel_launch(void* const* d_in, const int* in_sizes, int n_in,
                              void* d_out, int out_size) {
    const float* x   = (const float*)d_in[0];
    const int*   ei  = (const int*)d_in[1];
    const float* W1a = (const float*)d_in[2];
    const float* b1a = (const float*)d_in[3];
    const float* W1b = (const float*)d_in[4];
    const float* b1b = (const float*)d_in[5];
    const float* W2a = (const float*)d_in[6];
    const float* b2a = (const float*)d_in[7];
    const float* W2b = (const float*)d_in[8];
    const float* b2b = (const float*)d_in[9];
    const float* Wl  = (const float*)d_in[10];
    const float* bl  = (const float*)d_in[11];
    float* out = (float*)d_out;

    cudaFuncSetAttribute(k_mma, cudaFuncAttributeMaxDynamicSharedMemorySize, SMEM_BYTES);

    k_zero<<<(NN + 255) / 256, 256>>>();
    k_count<<<(EE + 255) / 256, 256>>>(ei);
    k_scan1<<<NSCANB, 1024>>>();
    k_scan2<<<1, 32>>>();
    k_scan3<<<NSCANB, 1024>>>();
    k_zero<<<(NN + 255) / 256, 256>>>();
    k_fill<<<(EE + 255) / 256, 256>>>(ei);

    k_uv1<<<(NN + 3) / 4, 128>>>(x, W1a, b1a);
    k_zeroagg<<<(NN * 64 + 1023) / 1024, 1024>>>();
    k_mma<<<296, 256, SMEM_BYTES>>>(W1b);
    k_post1<<<(NN * 64 + 1023) / 1024, 1024>>>(b1b);

    k_uv2<<<888, 128>>>(W2a, b2a);
    k_zeroagg<<<(NN * 64 + 1023) / 1024, 1024>>>();
    k_mma<<<296, 256, SMEM_BYTES>>>(W2b);
    k_final<<<(NN + 3) / 4, 128>>>(b2b, Wl, bl, out);
}

// round 13
// speedup vs baseline: 2.0283x; 1.4805x over previous
#include <cuda_runtime.h>
#include <cstdint>
#include <math_constants.h>

#define NN 100000
#define EE 1600000
#define TILE 128
#define NTILE (EE / TILE)          // 12500 exactly
#define NSCANB 98
#define BSTRIDE 72                 // == 8 mod 32 -> conflict-free v2 reads
#define DSTRIDE 133
#define USTRIDE 72
#define NODE_TILES 782             // ceil(100000/128)

// ---------------- static device scratch ----------------------------------
__device__ int      g_cnt[NN];
__device__ int      g_off[NN];
__device__ int      g_rank[EE];
__device__ int      g_bsum[NSCANB];
__device__ int      g_srcs[EE];
__device__ int      g_enode[EE];
__device__ __align__(256) float    g_U[NN * 64];
__device__ __align__(256) float    g_V[NN * 64];
__device__ __align__(256) unsigned g_agg1[NN * 64];
__device__ __align__(256) unsigned g_agg2[NN * 64];

// ---------------- helpers -------------------------------------------------
__device__ __forceinline__ uint32_t tf32(float f) {
    uint32_t r;
    asm("cvt.rna.tf32.f32 %0, %1;" : "=r"(r) : "f"(f));
    return r;
}
__device__ __forceinline__ unsigned ord_enc(float f) {
    unsigned u = __float_as_uint(f);
    return (u & 0x80000000u) ? ~u : (u | 0x80000000u);
}
__device__ __forceinline__ float ord_dec(unsigned u) {
    return (u & 0x80000000u) ? __uint_as_float(u ^ 0x80000000u) : __uint_as_float(~u);
}
__device__ __forceinline__ void redmax(unsigned* p, unsigned v) {
    asm volatile("red.global.max.u32 [%0], %1;" :: "l"(p), "r"(v) : "memory");
}
// column permutation: pairs (k, k+4) adjacent within each 8-group
__device__ __forceinline__ int gcol(int k) {
    return ((k >> 3) << 3) + ((k & 3) << 1) + ((k >> 2) & 1);
}
__device__ __forceinline__ uint32_t sptr(const void* p) {
    return (uint32_t)__cvta_generic_to_shared(p);
}
__device__ __forceinline__ void lds_v2(uint32_t& a, uint32_t& b, uint32_t addr) {
    asm volatile("ld.shared.v2.b32 {%0,%1}, [%2];"
                 : "=r"(a), "=r"(b) : "r"(addr) : "memory");
}

// ---------------- k_init: zero scratch + layer-1 U,V (K=7) ----------------
__global__ void __launch_bounds__(1024) k_init(const float* __restrict__ x,
                                               const float* __restrict__ W1a,
                                               const float* __restrict__ b1a) {
    unsigned i = blockIdx.x * 1024u + threadIdx.x;
    if (i < NN * 64) { g_agg1[i] = 0u; g_agg2[i] = 0u; }
    if (i < NN) g_cnt[i] = 0;

    if (blockIdx.x < 3125) {
        __shared__ float sW[14 * 64];
        __shared__ float sb[64];
        for (int t = threadIdx.x; t < 14 * 64; t += 1024) sW[t] = W1a[t];
        for (int t = threadIdx.x; t < 64; t += 1024) sb[t] = b1a[t];
        __syncthreads();
        int wid = threadIdx.x >> 5, lane = threadIdx.x & 31;
        int n = blockIdx.x * 32 + wid;          // 3125*32 = 100000 exactly
        int c0 = 2 * lane, c1 = c0 + 1;
        float xv[7];
#pragma unroll
        for (int k = 0; k < 7; k++) xv[k] = x[n * 7 + k];
        float u0 = sb[c0], u1 = sb[c1], v0 = 0.f, v1 = 0.f;
#pragma unroll
        for (int k = 0; k < 7; k++) {
            float wt0 = sW[k * 64 + c0], wt1 = sW[k * 64 + c1];
            float wb0 = sW[(7 + k) * 64 + c0], wb1 = sW[(7 + k) * 64 + c1];
            u0 = fmaf(xv[k], wt0 - wb0, u0);
            u1 = fmaf(xv[k], wt1 - wb1, u1);
            v0 = fmaf(xv[k], wb0, v0);
            v1 = fmaf(xv[k], wb1, v1);
        }
        *(float2*)&g_U[n * 64 + c0] = make_float2(u0, u1);
        *(float2*)&g_V[n * 64 + c0] = make_float2(v0, v1);
    }
}

// ---------------- count + rank --------------------------------------------
__global__ void k_count(const int* __restrict__ ei) {
    int e = blockIdx.x * blockDim.x + threadIdx.x;
    if (e < EE) {
        int d = ei[EE + e];
        g_rank[e] = atomicAdd(&g_cnt[d], 1);
    }
}

// ---------------- 3-kernel exclusive scan (round-7-proven) ----------------
__global__ void __launch_bounds__(1024) k_scan1() {
    __shared__ int ws[32];
    int i = blockIdx.x * 1024 + threadIdx.x;
    int v = (i < NN) ? g_cnt[i] : 0;
    int x = v;
#pragma unroll
    for (int o = 1; o < 32; o <<= 1) {
        int y = __shfl_up_sync(0xffffffffu, x, o);
        if ((threadIdx.x & 31) >= o) x += y;
    }
    if ((threadIdx.x & 31) == 31) ws[threadIdx.x >> 5] = x;
    __syncthreads();
    if (threadIdx.x < 32) {
        int y = ws[threadIdx.x];
#pragma unroll
        for (int o = 1; o < 32; o <<= 1) {
            int z = __shfl_up_sync(0xffffffffu, y, o);
            if (threadIdx.x >= o) y += z;
        }
        ws[threadIdx.x] = y;
    }
    __syncthreads();
    int wsum = (threadIdx.x >= 32) ? ws[(threadIdx.x >> 5) - 1] : 0;
    int incl = x + wsum;
    if (i < NN) g_off[i] = incl - v;
    if (threadIdx.x == 1023) g_bsum[blockIdx.x] = incl;
}
__global__ void k_scan2() {
    if (threadIdx.x == 0) {
        int run = 0;
        for (int b = 0; b < NSCANB; b++) { int t = g_bsum[b]; g_bsum[b] = run; run += t; }
    }
}
__global__ void __launch_bounds__(1024) k_scan3() {
    int i = blockIdx.x * 1024 + threadIdx.x;
    if (i < NN) g_off[i] += g_bsum[blockIdx.x];
}

// ---------------- fill sorted edge arrays (no atomics) --------------------
__global__ void k_fill(const int* __restrict__ ei) {
    int e = blockIdx.x * blockDim.x + threadIdx.x;
    if (e >= EE) return;
    int s = ei[e], d = ei[EE + e];
    int idx = g_off[d] + g_rank[e];
    g_srcs[idx] = s;
    g_enode[idx] = d;
}

// ---------------- hot kernel: tf32 mma.sync over sorted edge tiles --------
// LAYER template selects the agg buffer IN DEVICE CODE (host-side &__device__
// symbol is the host shadow address -> silent ATS writes to host memory).
#define MMA_SMEM_WORDS (TILE * BSTRIDE + 64 * DSTRIDE + TILE)
#define MMA_SMEM_BYTES (MMA_SMEM_WORDS * 4)

template <int LAYER>
__global__ void __launch_bounds__(256, 2) k_mma(const float* __restrict__ Wb) {
    unsigned* __restrict__ agg = (LAYER == 0) ? g_agg1 : g_agg2;
    extern __shared__ uint32_t smem[];
    uint32_t* Bs = smem;                                    // [128][BSTRIDE]
    float*    Ds = (float*)(smem + TILE * BSTRIDE);         // [64][DSTRIDE]
    int*   snode = (int*)(smem + TILE * BSTRIDE + 64 * DSTRIDE);

    const int tid = threadIdx.x, wid = tid >> 5, lane = tid & 31;
    const int g = lane >> 2, r = lane & 3;
    const int m0 = 16 * (wid & 3);
    const int n0b = 64 * (wid >> 2);

    // preload A fragments (Wb^T, rna-tf32)
    uint32_t aw[8][4];
#pragma unroll
    for (int kk = 0; kk < 8; kk++) {
        int k0 = kk * 8 + r;
        aw[kk][0] = tf32(Wb[k0 * 64 + m0 + g]);
        aw[kk][1] = tf32(Wb[k0 * 64 + m0 + g + 8]);
        aw[kk][2] = tf32(Wb[(k0 + 4) * 64 + m0 + g]);
        aw[kk][3] = tf32(Wb[(k0 + 4) * 64 + m0 + g + 8]);
    }

    const int eL = tid & 127, hf = tid >> 7;    // edge-in-tile, k-half

    for (int tt = blockIdx.x; tt < NTILE; tt += gridDim.x) {
        int e0 = tt * TILE;
        // ---- build B tile: 2 threads per edge, float4 row-half gathers
        {
            int s = g_srcs[e0 + eL], d = g_enode[e0 + eL];
            if (tid < 128) snode[tid] = d;
            const float4* up = (const float4*)&g_U[d * 64 + hf * 32];
            const float4* vp = (const float4*)&g_V[s * 64 + hf * 32];
            float4 u4[8], v4[8];
#pragma unroll
            for (int j = 0; j < 8; j++) u4[j] = up[j];
#pragma unroll
            for (int j = 0; j < 8; j++) v4[j] = vp[j];
            const float* uf = (const float*)u4;
            const float* vf = (const float*)v4;
            uint32_t baddr = sptr(&Bs[eL * BSTRIDE + hf * 32]);
#pragma unroll
            for (int gg = 0; gg < 4; gg++) {
                uint32_t t[8];
#pragma unroll
                for (int q = 0; q < 8; q++)
                    t[q] = tf32(fmaxf(uf[gg * 8 + q] + vf[gg * 8 + q], 0.f));
                asm volatile("st.shared.v4.b32 [%0], {%1,%2,%3,%4};"
                             :: "r"(baddr + gg * 32), "r"(t[0]), "r"(t[4]), "r"(t[1]), "r"(t[5]) : "memory");
                asm volatile("st.shared.v4.b32 [%0], {%1,%2,%3,%4};"
                             :: "r"(baddr + gg * 32 + 16), "r"(t[2]), "r"(t[6]), "r"(t[3]), "r"(t[7]) : "memory");
            }
        }
        __syncthreads();

        // ---- MMA: warp covers ch [m0,m0+16) x edges [n0b, n0b+64)
#pragma unroll
        for (int j = 0; j < 8; j++) {
            int n0 = n0b + 8 * j;
            float c0 = 0.f, c1 = 0.f, c2 = 0.f, c3 = 0.f;
            uint32_t bp = sptr(&Bs[(n0 + g) * BSTRIDE + 2 * r]);
#pragma unroll
            for (int kk = 0; kk < 8; kk++) {
                uint32_t b0, b1;
                lds_v2(b0, b1, bp + 32 * kk);
                asm volatile(
                    "mma.sync.aligned.m16n8k8.row.col.f32.tf32.tf32.f32 "
                    "{%0,%1,%2,%3}, {%4,%5,%6,%7}, {%8,%9}, {%0,%1,%2,%3};"
                    : "+f"(c0), "+f"(c1), "+f"(c2), "+f"(c3)
                    : "r"(aw[kk][0]), "r"(aw[kk][1]), "r"(aw[kk][2]), "r"(aw[kk][3]),
                      "r"(b0), "r"(b1));
            }
            int e = n0 + 2 * r;
            Ds[(m0 + g) * DSTRIDE + e]         = c0;
            Ds[(m0 + g) * DSTRIDE + e + 1]     = c1;
            Ds[(m0 + g + 8) * DSTRIDE + e]     = c2;
            Ds[(m0 + g + 8) * DSTRIDE + e + 1] = c3;
        }
        __syncthreads();

        // ---- epilogue: segmented max; thread = (channel, edge-quarter)
        {
            int ch = tid & 63, qq = tid >> 6;
            int es = qq * 32;
            float acc = -CUDART_INF_F;
            int cur = snode[es];
            const float* dp = &Ds[ch * DSTRIDE];
#pragma unroll 8
            for (int e = es; e < es + 32; e++) {
                int nid = snode[e];
                float v = dp[e];
                if (nid != cur) {
                    redmax(&agg[cur * 64 + ch], ord_enc(acc));
                    cur = nid;
                    acc = -CUDART_INF_F;
                }
                acc = fmaxf(acc, v);
            }
            redmax(&agg[cur * 64 + ch], ord_enc(acc));
        }
        __syncthreads();
    }
}

// ---------------- fused layer-2 U,V: h = relu(agg1+b1b); [U|V] = h@Wc -----
#define UV_SMEM_WORDS (2 * 128 * USTRIDE + 128)
#define UV_SMEM_BYTES (UV_SMEM_WORDS * 4)

__global__ void __launch_bounds__(256, 2) k_uvmma(const float* __restrict__ W2a,
                                                  const float* __restrict__ b2a,
                                                  const float* __restrict__ b1b) {
    extern __shared__ uint32_t sm2[];
    uint32_t* Hs = sm2;                          // [128 nodes][USTRIDE]
    uint32_t* Ws = sm2 + 128 * USTRIDE;          // [128 outs][USTRIDE]
    float* sb2 = (float*)(sm2 + 2 * 128 * USTRIDE);
    float* sb1 = sb2 + 64;

    int tid = threadIdx.x, wid = tid >> 5, lane = tid & 31;
    int g = lane >> 2, r = lane & 3;
    if (tid < 64) { sb2[tid] = b2a[tid]; sb1[tid] = b1b[tid]; }
    // stage combined weights:  out n<64: Wt-Wb (U),  n>=64: Wb (V)
    for (int i = tid; i < 128 * 64; i += 256) {
        int n = i >> 6, k = i & 63;
        float w = (n < 64) ? (W2a[k * 64 + n] - W2a[(64 + k) * 64 + n])
                           : W2a[(64 + k) * 64 + (n - 64)];
        Ws[n * USTRIDE + gcol(k)] = tf32(w);
    }
    __syncthreads();

    int m0 = wid * 16;
    for (int tt = blockIdx.x; tt < NODE_TILES; tt += gridDim.x) {
        int base = tt * 128;
        // build h tile (bias + relu + NaN->0 for empty nodes)
        for (int i = tid; i < 128 * 32; i += 256) {
            int row = i >> 5, kp = i & 31;
            int gg = kp >> 2, q = kp & 3, k = gg * 8 + q;
            int node = base + row;
            float h0 = 0.f, h1 = 0.f;
            if (node < NN) {
                h0 = fmaxf(ord_dec(g_agg1[node * 64 + k]) + sb1[k], 0.f);
                h1 = fmaxf(ord_dec(g_agg1[node * 64 + k + 4]) + sb1[k + 4], 0.f);
            }
            uint32_t q0 = tf32(h0), q1 = tf32(h1);
            asm volatile("st.shared.v2.b32 [%0], {%1,%2};"
                         :: "r"(sptr(&Hs[row * USTRIDE + gg * 8 + 2 * q])), "r"(q0), "r"(q1) : "memory");
        }
        __syncthreads();
        // A fragments for this warp's 16 nodes
        uint32_t a[8][4];
#pragma unroll
        for (int kk = 0; kk < 8; kk++) {
            lds_v2(a[kk][0], a[kk][2], sptr(&Hs[(m0 + g) * USTRIDE + 2 * r + 8 * kk]));
            lds_v2(a[kk][1], a[kk][3], sptr(&Hs[(m0 + g + 8) * USTRIDE + 2 * r + 8 * kk]));
        }
#pragma unroll
        for (int j = 0; j < 16; j++) {
            float c0 = 0.f, c1 = 0.f, c2 = 0.f, c3 = 0.f;
            uint32_t wp = sptr(&Ws[(8 * j + g) * USTRIDE + 2 * r]);
#pragma unroll
            for (int kk = 0; kk < 8; kk++) {
                uint32_t b0, b1;
                lds_v2(b0, b1, wp + 32 * kk);
                asm volatile(
                    "mma.sync.aligned.m16n8k8.row.col.f32.tf32.tf32.f32 "
                    "{%0,%1,%2,%3}, {%4,%5,%6,%7}, {%8,%9}, {%0,%1,%2,%3};"
                    : "+f"(c0), "+f"(c1), "+f"(c2), "+f"(c3)
                    : "r"(a[kk][0]), "r"(a[kk][1]), "r"(a[kk][2]), "r"(a[kk][3]),
                      "r"(b0), "r"(b1));
            }
            int col = 8 * j + 2 * r;
            int n1 = base + m0 + g, n2 = n1 + 8;
            if (col < 64) {
                float bx = sb2[col], by = sb2[col + 1];
                if (n1 < NN) *(float2*)&g_U[n1 * 64 + col] = make_float2(c0 + bx, c1 + by);
                if (n2 < NN) *(float2*)&g_U[n2 * 64 + col] = make_float2(c2 + bx, c3 + by);
            } else {
                int cc = col - 64;
                if (n1 < NN) *(float2*)&g_V[n1 * 64 + cc] = make_float2(c0, c1);
                if (n2 < NN) *(float2*)&g_V[n2 * 64 + cc] = make_float2(c2, c3);
            }
        }
        __syncthreads();
    }
}

// ---------------- final head ----------------------------------------------
__global__ void __launch_bounds__(128) k_final(const float* __restrict__ b2b,
                                               const float* __restrict__ Wl,
                                               const float* __restrict__ bl,
                                               float* __restrict__ out) {
    int warp = threadIdx.x >> 5, lane = threadIdx.x & 31;
    int i = blockIdx.x * 4 + warp;
    if (i >= NN) return;
    int c0 = 2 * lane, c1 = c0 + 1;
    float a0 = fmaxf(ord_dec(g_agg2[i * 64 + c0]) + b2b[c0], 0.f);
    float a1 = fmaxf(ord_dec(g_agg2[i * 64 + c1]) + b2b[c1], 0.f);
    float p = a0 * Wl[c0] + a1 * Wl[c1];
#pragma unroll
    for (int off = 16; off; off >>= 1) p += __shfl_xor_sync(0xffffffffu, p, off);
    if (lane == 0) out[i] = p + bl[0];
}

extern "C" void kernel_launch(void* const* d_in, const int* in_sizes, int n_in,
                              void* d_out, int out_size) {
    const float* x   = (const float*)d_in[0];
    const int*   ei  = (const int*)d_in[1];
    const float* W1a = (const float*)d_in[2];
    const float* b1a = (const float*)d_in[3];
    const float* W1b = (const float*)d_in[4];
    const float* b1b = (const float*)d_in[5];
    const float* W2a = (const float*)d_in[6];
    const float* b2a = (const float*)d_in[7];
    const float* W2b = (const float*)d_in[8];
    const float* b2b = (const float*)d_in[9];
    const float* Wl  = (const float*)d_in[10];
    const float* bl  = (const float*)d_in[11];
    float* out = (float*)d_out;

    cudaFuncSetAttribute(k_mma<0>, cudaFuncAttributeMaxDynamicSharedMemorySize, MMA_SMEM_BYTES);
    cudaFuncSetAttribute(k_mma<1>, cudaFuncAttributeMaxDynamicSharedMemorySize, MMA_SMEM_BYTES);
    cudaFuncSetAttribute(k_uvmma, cudaFuncAttributeMaxDynamicSharedMemorySize, UV_SMEM_BYTES);

    k_init<<<6250, 1024>>>(x, W1a, b1a);
    k_count<<<(EE + 255) / 256, 256>>>(ei);
    k_scan1<<<NSCANB, 1024>>>();
    k_scan2<<<1, 32>>>();
    k_scan3<<<NSCANB, 1024>>>();
    k_fill<<<(EE + 255) / 256, 256>>>(ei);
    k_mma<0><<<296, 256, MMA_SMEM_BYTES>>>(W1b);
    k_uvmma<<<296, 256, UV_SMEM_BYTES>>>(W2a, b2a, b1b);
    k_mma<1><<<296, 256, MMA_SMEM_BYTES>>>(W2b);
    k_final<<<(NN + 3) / 4, 128>>>(b2b, Wl, bl, out);
}

// round 14
// speedup vs baseline: 2.4899x; 1.2276x over previous
#include <cuda_runtime.h>
#include <cstdint>
#include <math_constants.h>

#define NN 100000
#define EE 1600000
#define TILE 128
#define NTILE (EE / TILE)          // 12500 exactly
#define NSCANB 98
#define BSTRIDE 72                 // == 8 mod 32 -> conflict-free v2 reads
#define DSTRIDE 133
#define USTRIDE 72
#define NODE_TILES 782             // ceil(100000/128)

// ---------------- static device scratch ----------------------------------
__device__ int      g_cnt[NN];
__device__ int      g_off[NN];
__device__ int      g_rank[EE];
__device__ int      g_bsum[NSCANB];
__device__ int      g_srcs[EE];
__device__ int      g_enode[EE];
// g_U/g_V columns stored in gcol-PERMUTED order (MMA fragment pairing)
__device__ __align__(256) float    g_U[NN * 64];
__device__ __align__(256) float    g_V[NN * 64];
__device__ __align__(256) unsigned g_agg1[NN * 64];
__device__ __align__(256) unsigned g_agg2[NN * 64];

// ---------------- helpers -------------------------------------------------
__device__ __forceinline__ uint32_t tf32(float f) {
    uint32_t r;
    asm("cvt.rna.tf32.f32 %0, %1;" : "=r"(r) : "f"(f));
    return r;
}
__device__ __forceinline__ unsigned ord_enc(float f) {
    unsigned u = __float_as_uint(f);
    return (u & 0x80000000u) ? ~u : (u | 0x80000000u);
}
__device__ __forceinline__ float ord_dec(unsigned u) {
    return (u & 0x80000000u) ? __uint_as_float(u ^ 0x80000000u) : __uint_as_float(~u);
}
__device__ __forceinline__ void redmax(unsigned* p, unsigned v) {
    asm volatile("red.global.max.u32 [%0], %1;" :: "l"(p), "r"(v) : "memory");
}
// column permutation: pairs (k, k+4) adjacent within each 8-group
__device__ __forceinline__ int gcol(int k) {
    return ((k >> 3) << 3) + ((k & 3) << 1) + ((k >> 2) & 1);
}
__device__ __forceinline__ uint32_t sptr(const void* p) {
    return (uint32_t)__cvta_generic_to_shared(p);
}
__device__ __forceinline__ void lds_v2(uint32_t& a, uint32_t& b, uint32_t addr) {
    asm volatile("ld.shared.v2.b32 {%0,%1}, [%2];"
                 : "=r"(a), "=r"(b) : "r"(addr) : "memory");
}

// ---------------- k_init: zero scratch + layer-1 U,V (K=7, permuted) ------
__global__ void __launch_bounds__(1024) k_init(const float* __restrict__ x,
                                               const float* __restrict__ W1a,
                                               const float* __restrict__ b1a) {
    unsigned i = blockIdx.x * 1024u + threadIdx.x;
    if (i < NN * 64) { g_agg1[i] = 0u; g_agg2[i] = 0u; }
    if (i < NN) g_cnt[i] = 0;

    if (blockIdx.x < 3125) {
        __shared__ float sW[14 * 64];
        __shared__ float sb[64];
        for (int t = threadIdx.x; t < 14 * 64; t += 1024) sW[t] = W1a[t];
        for (int t = threadIdx.x; t < 64; t += 1024) sb[t] = b1a[t];
        __syncthreads();
        int wid = threadIdx.x >> 5, lane = threadIdx.x & 31;
        int n = blockIdx.x * 32 + wid;          // 3125*32 = 100000 exactly
        int c0 = 2 * lane, c1 = c0 + 1;
        float xv[7];
#pragma unroll
        for (int k = 0; k < 7; k++) xv[k] = x[n * 7 + k];
        float u0 = sb[c0], u1 = sb[c1], v0 = 0.f, v1 = 0.f;
#pragma unroll
        for (int k = 0; k < 7; k++) {
            float wt0 = sW[k * 64 + c0], wt1 = sW[k * 64 + c1];
            float wb0 = sW[(7 + k) * 64 + c0], wb1 = sW[(7 + k) * 64 + c1];
            u0 = fmaf(xv[k], wt0 - wb0, u0);
            u1 = fmaf(xv[k], wt1 - wb1, u1);
            v0 = fmaf(xv[k], wb0, v0);
            v1 = fmaf(xv[k], wb1, v1);
        }
        int p0 = gcol(c0), p1 = gcol(c1);
        g_U[n * 64 + p0] = u0; g_U[n * 64 + p1] = u1;
        g_V[n * 64 + p0] = v0; g_V[n * 64 + p1] = v1;
    }
}

// ---------------- count + rank --------------------------------------------
__global__ void k_count(const int* __restrict__ ei) {
    int e = blockIdx.x * blockDim.x + threadIdx.x;
    if (e < EE) {
        int d = ei[EE + e];
        g_rank[e] = atomicAdd(&g_cnt[d], 1);
    }
}

// ---------------- 3-kernel exclusive scan ---------------------------------
__global__ void __launch_bounds__(1024) k_scan1() {
    __shared__ int ws[32];
    int i = blockIdx.x * 1024 + threadIdx.x;
    int v = (i < NN) ? g_cnt[i] : 0;
    int x = v;
#pragma unroll
    for (int o = 1; o < 32; o <<= 1) {
        int y = __shfl_up_sync(0xffffffffu, x, o);
        if ((threadIdx.x & 31) >= o) x += y;
    }
    if ((threadIdx.x & 31) == 31) ws[threadIdx.x >> 5] = x;
    __syncthreads();
    if (threadIdx.x < 32) {
        int y = ws[threadIdx.x];
#pragma unroll
        for (int o = 1; o < 32; o <<= 1) {
            int z = __shfl_up_sync(0xffffffffu, y, o);
            if (threadIdx.x >= o) y += z;
        }
        ws[threadIdx.x] = y;
    }
    __syncthreads();
    int wsum = (threadIdx.x >= 32) ? ws[(threadIdx.x >> 5) - 1] : 0;
    int incl = x + wsum;
    if (i < NN) g_off[i] = incl - v;
    if (threadIdx.x == 1023) g_bsum[blockIdx.x] = incl;
}
__global__ void __launch_bounds__(128) k_scan2() {
    __shared__ int ws[4];
    int t = threadIdx.x, lane = t & 31, wp = t >> 5;
    int v = (t < NSCANB) ? g_bsum[t] : 0;
    int x = v;
#pragma unroll
    for (int o = 1; o < 32; o <<= 1) {
        int y = __shfl_up_sync(0xffffffffu, x, o);
        if (lane >= o) x += y;
    }
    if (lane == 31) ws[wp] = x;
    __syncthreads();
    int base = 0;
#pragma unroll
    for (int w = 0; w < 4; w++) if (w < wp) base += ws[w];
    if (t < NSCANB) g_bsum[t] = base + x - v;   // exclusive
}
__global__ void __launch_bounds__(1024) k_scan3() {
    int i = blockIdx.x * 1024 + threadIdx.x;
    if (i < NN) g_off[i] += g_bsum[blockIdx.x];
}

// ---------------- fill sorted edge arrays (no atomics) --------------------
__global__ void k_fill(const int* __restrict__ ei) {
    int e = blockIdx.x * blockDim.x + threadIdx.x;
    if (e >= EE) return;
    int s = ei[e], d = ei[EE + e];
    int idx = g_off[d] + g_rank[e];
    g_srcs[idx] = s;
    g_enode[idx] = d;
}

// ---------------- hot kernel: tf32 mma.sync over sorted edge tiles --------
#define MMA_SMEM_WORDS (TILE * BSTRIDE + 64 * DSTRIDE + TILE)
#define MMA_SMEM_BYTES (MMA_SMEM_WORDS * 4)

template <int LAYER>
__global__ void __launch_bounds__(256, 2) k_mma(const float* __restrict__ Wb) {
    unsigned* __restrict__ agg = (LAYER == 0) ? g_agg1 : g_agg2;
    extern __shared__ uint32_t smem[];
    uint32_t* Bs = smem;                                    // [128][BSTRIDE]
    float*    Ds = (float*)(smem + TILE * BSTRIDE);         // [64][DSTRIDE]
    int*   snode = (int*)(smem + TILE * BSTRIDE + 64 * DSTRIDE);

    const int tid = threadIdx.x, wid = tid >> 5, lane = tid & 31;
    const int g = lane >> 2, r = lane & 3;
    const int m0 = 16 * (wid & 3);
    const int n0b = 64 * (wid >> 2);

    // preload A fragments (Wb^T, rna-tf32); pair order (k, k+4) matches the
    // permuted B layout by construction
    uint32_t aw[8][4];
#pragma unroll
    for (int kk = 0; kk < 8; kk++) {
        int k0 = kk * 8 + r;
        aw[kk][0] = tf32(Wb[k0 * 64 + m0 + g]);
        aw[kk][1] = tf32(Wb[k0 * 64 + m0 + g + 8]);
        aw[kk][2] = tf32(Wb[(k0 + 4) * 64 + m0 + g]);
        aw[kk][3] = tf32(Wb[(k0 + 4) * 64 + m0 + g + 8]);
    }

    const int half = lane >> 4, l16 = lane & 15;   // build-phase lane split

    for (int tt = blockIdx.x; tt < NTILE; tt += gridDim.x) {
        int e0w = tt * TILE + wid * 16;
        // ---- build B tile: 16 lanes per node row -> nL=4 lines/LDG
        {
            int myv = (lane < 16) ? g_srcs[e0w + lane] : g_enode[e0w + (lane - 16)];
            if (lane >= 16) snode[wid * 16 + lane - 16] = myv;
#pragma unroll
            for (int j = 0; j < 8; j++) {
                int ei2 = 2 * j + half;                       // edge in [0,16)
                int s = __shfl_sync(0xffffffffu, myv, ei2);
                int d = __shfl_sync(0xffffffffu, myv, 16 + ei2);
                float4 u = *(const float4*)&g_U[d * 64 + 4 * l16];
                float4 v = *(const float4*)&g_V[s * 64 + 4 * l16];
                uint32_t t0 = tf32(fmaxf(u.x + v.x, 0.f));
                uint32_t t1 = tf32(fmaxf(u.y + v.y, 0.f));
                uint32_t t2 = tf32(fmaxf(u.z + v.z, 0.f));
                uint32_t t3 = tf32(fmaxf(u.w + v.w, 0.f));
                uint32_t addr = sptr(&Bs[(wid * 16 + ei2) * BSTRIDE + 4 * l16]);
                asm volatile("st.shared.v4.b32 [%0], {%1,%2,%3,%4};"
                             :: "r"(addr), "r"(t0), "r"(t1), "r"(t2), "r"(t3) : "memory");
            }
        }
        __syncthreads();

        // ---- MMA: warp covers ch [m0,m0+16) x edges [n0b, n0b+64)
#pragma unroll
        for (int j = 0; j < 8; j++) {
            int n0 = n0b + 8 * j;
            float c0 = 0.f, c1 = 0.f, c2 = 0.f, c3 = 0.f;
            uint32_t bp = sptr(&Bs[(n0 + g) * BSTRIDE + 2 * r]);
#pragma unroll
            for (int kk = 0; kk < 8; kk++) {
                uint32_t b0, b1;
                lds_v2(b0, b1, bp + 32 * kk);
                asm volatile(
                    "mma.sync.aligned.m16n8k8.row.col.f32.tf32.tf32.f32 "
                    "{%0,%1,%2,%3}, {%4,%5,%6,%7}, {%8,%9}, {%0,%1,%2,%3};"
                    : "+f"(c0), "+f"(c1), "+f"(c2), "+f"(c3)
                    : "r"(aw[kk][0]), "r"(aw[kk][1]), "r"(aw[kk][2]), "r"(aw[kk][3]),
                      "r"(b0), "r"(b1));
            }
            int e = n0 + 2 * r;
            Ds[(m0 + g) * DSTRIDE + e]         = c0;
            Ds[(m0 + g) * DSTRIDE + e + 1]     = c1;
            Ds[(m0 + g + 8) * DSTRIDE + e]     = c2;
            Ds[(m0 + g + 8) * DSTRIDE + e + 1] = c3;
        }
        __syncthreads();

        // ---- epilogue: segmented max; thread = (channel, edge-quarter)
        {
            int ch = tid & 63, qq = tid >> 6;
            int es = qq * 32;
            float acc = -CUDART_INF_F;
            int cur = snode[es];
            const float* dp = &Ds[ch * DSTRIDE];
#pragma unroll 8
            for (int e = es; e < es + 32; e++) {
                int nid = snode[e];
                float v = dp[e];
                if (nid != cur) {
                    redmax(&agg[cur * 64 + ch], ord_enc(acc));
                    cur = nid;
                    acc = -CUDART_INF_F;
                }
                acc = fmaxf(acc, v);
            }
            redmax(&agg[cur * 64 + ch], ord_enc(acc));
        }
        __syncthreads();
    }
}

// ---------------- fused layer-2 U,V: h = relu(agg1+b1b); [U|V] = h@Wc -----
#define UV_SMEM_WORDS (2 * 128 * USTRIDE + 128)
#define UV_SMEM_BYTES (UV_SMEM_WORDS * 4)

__global__ void __launch_bounds__(256, 2) k_uvmma(const float* __restrict__ W2a,
                                                  const float* __restrict__ b2a,
                                                  const float* __restrict__ b1b) {
    extern __shared__ uint32_t sm2[];
    uint32_t* Hs = sm2;                          // [128 nodes][USTRIDE]
    uint32_t* Ws = sm2 + 128 * USTRIDE;          // [128 outs][USTRIDE]
    float* sb2 = (float*)(sm2 + 2 * 128 * USTRIDE);
    float* sb1 = sb2 + 64;

    int tid = threadIdx.x, wid = tid >> 5, lane = tid & 31;
    int g = lane >> 2, r = lane & 3;
    if (tid < 64) { sb2[tid] = b2a[tid]; sb1[tid] = b1b[tid]; }
    // stage combined weights:  out n<64: Wt-Wb (U),  n>=64: Wb (V)
    for (int i = tid; i < 128 * 64; i += 256) {
        int n = i >> 6, k = i & 63;
        float w = (n < 64) ? (W2a[k * 64 + n] - W2a[(64 + k) * 64 + n])
                           : W2a[(64 + k) * 64 + (n - 64)];
        Ws[n * USTRIDE + gcol(k)] = tf32(w);
    }
    __syncthreads();

    int m0 = wid * 16;
    for (int tt = blockIdx.x; tt < NODE_TILES; tt += gridDim.x) {
        int base = tt * 128;
        // build h tile (bias + relu + NaN->0 for empty nodes)
        for (int i = tid; i < 128 * 32; i += 256) {
            int row = i >> 5, kp = i & 31;
            int gg = kp >> 2, q = kp & 3, k = gg * 8 + q;
            int node = base + row;
            float h0 = 0.f, h1 = 0.f;
            if (node < NN) {
                h0 = fmaxf(ord_dec(g_agg1[node * 64 + k]) + sb1[k], 0.f);
                h1 = fmaxf(ord_dec(g_agg1[node * 64 + k + 4]) + sb1[k + 4], 0.f);
            }
            uint32_t q0 = tf32(h0), q1 = tf32(h1);
            asm volatile("st.shared.v2.b32 [%0], {%1,%2};"
                         :: "r"(sptr(&Hs[row * USTRIDE + gg * 8 + 2 * q])), "r"(q0), "r"(q1) : "memory");
        }
        __syncthreads();
        // A fragments for this warp's 16 nodes
        uint32_t a[8][4];
#pragma unroll
        for (int kk = 0; kk < 8; kk++) {
            lds_v2(a[kk][0], a[kk][2], sptr(&Hs[(m0 + g) * USTRIDE + 2 * r + 8 * kk]));
            lds_v2(a[kk][1], a[kk][3], sptr(&Hs[(m0 + g + 8) * USTRIDE + 2 * r + 8 * kk]));
        }
#pragma unroll
        for (int j = 0; j < 16; j++) {
            float c0 = 0.f, c1 = 0.f, c2 = 0.f, c3 = 0.f;
            uint32_t wp = sptr(&Ws[(8 * j + g) * USTRIDE + 2 * r]);
#pragma unroll
            for (int kk = 0; kk < 8; kk++) {
                uint32_t b0, b1;
                lds_v2(b0, b1, wp + 32 * kk);
                asm volatile(
                    "mma.sync.aligned.m16n8k8.row.col.f32.tf32.tf32.f32 "
                    "{%0,%1,%2,%3}, {%4,%5,%6,%7}, {%8,%9}, {%0,%1,%2,%3};"
                    : "+f"(c0), "+f"(c1), "+f"(c2), "+f"(c3)
                    : "r"(a[kk][0]), "r"(a[kk][1]), "r"(a[kk][2]), "r"(a[kk][3]),
                      "r"(b0), "r"(b1));
            }
            int col = 8 * j + 2 * r;
            int n1 = base + m0 + g, n2 = n1 + 8;
            if (col < 64) {
                int p0 = gcol(col), p1 = gcol(col + 1);
                float bx = sb2[col], by = sb2[col + 1];
                if (n1 < NN) { g_U[n1 * 64 + p0] = c0 + bx; g_U[n1 * 64 + p1] = c1 + by; }
                if (n2 < NN) { g_U[n2 * 64 + p0] = c2 + bx; g_U[n2 * 64 + p1] = c3 + by; }
            } else {
                int p0 = gcol(col - 64), p1 = gcol(col - 63);
                if (n1 < NN) { g_V[n1 * 64 + p0] = c0; g_V[n1 * 64 + p1] = c1; }
                if (n2 < NN) { g_V[n2 * 64 + p0] = c2; g_V[n2 * 64 + p1] = c3; }
            }
        }
        __syncthreads();
    }
}

// ---------------- final head ----------------------------------------------
__global__ void __launch_bounds__(128) k_final(const float* __restrict__ b2b,
                                               const float* __restrict__ Wl,
                                               const float* __restrict__ bl,
                                               float* __restrict__ out) {
    int warp = threadIdx.x >> 5, lane = threadIdx.x & 31;
    int i = blockIdx.x * 4 + warp;
    if (i >= NN) return;
    int c0 = 2 * lane, c1 = c0 + 1;
    float a0 = fmaxf(ord_dec(g_agg2[i * 64 + c0]) + b2b[c0], 0.f);
    float a1 = fmaxf(ord_dec(g_agg2[i * 64 + c1]) + b2b[c1], 0.f);
    float p = a0 * Wl[c0] + a1 * Wl[c1];
#pragma unroll
    for (int off = 16; off; off >>= 1) p += __shfl_xor_sync(0xffffffffu, p, off);
    if (lane == 0) out[i] = p + bl[0];
}

extern "C" void kernel_launch(void* const* d_in, const int* in_sizes, int n_in,
                              void* d_out, int out_size) {
    const float* x   = (const float*)d_in[0];
    const int*   ei  = (const int*)d_in[1];
    const float* W1a = (const float*)d_in[2];
    const float* b1a = (const float*)d_in[3];
    const float* W1b = (const float*)d_in[4];
    const float* b1b = (const float*)d_in[5];
    const float* W2a = (const float*)d_in[6];
    const float* b2a = (const float*)d_in[7];
    const float* W2b = (const float*)d_in[8];
    const float* b2b = (const float*)d_in[9];
    const float* Wl  = (const float*)d_in[10];
    const float* bl  = (const float*)d_in[11];
    float* out = (float*)d_out;

    cudaFuncSetAttribute(k_mma<0>, cudaFuncAttributeMaxDynamicSharedMemorySize, MMA_SMEM_BYTES);
    cudaFuncSetAttribute(k_mma<1>, cudaFuncAttributeMaxDynamicSharedMemorySize, MMA_SMEM_BYTES);
    cudaFuncSetAttribute(k_uvmma, cudaFuncAttributeMaxDynamicSharedMemorySize, UV_SMEM_BYTES);

    k_init<<<6250, 1024>>>(x, W1a, b1a);
    k_count<<<(EE + 255) / 256, 256>>>(ei);
    k_scan1<<<NSCANB, 1024>>>();
    k_scan2<<<1, 128>>>();
    k_scan3<<<NSCANB, 1024>>>();
    k_fill<<<(EE + 255) / 256, 256>>>(ei);
    k_mma<0><<<296, 256, MMA_SMEM_BYTES>>>(W1b);
    k_uvmma<<<296, 256, UV_SMEM_BYTES>>>(W2a, b2a, b1b);
    k_mma<1><<<296, 256, MMA_SMEM_BYTES>>>(W2b);
    k_final<<<(NN + 3) / 4, 128>>>(b2b, Wl, bl, out);
}